// round 5
// baseline (speedup 1.0000x reference)
#include <cuda_runtime.h>
#include <cstdint>

// Problem constants (from reference)
#define DD   41
#define CCH  64
#define CHT  105          // DD + CCH
#define FH_  32
#define FW_  88
#define B_   4
#define NX0_ 200
#define NZ_  200
#define COLH (CHT * FH_)  // 3360 floats per (b,w) column in xT
#define DSPLIT 2
#define DCHUNK 21         // ceil(41/2)

// Static scratch
__device__ float g_xT[(size_t)B_ * FW_ * COLH];          // 4.73 MB
__device__ float g_V[(size_t)B_ * FW_ * DD * CCH];       // 3.69 MB
__device__ int   g_bin[B_ * DD * FW_];                   // packed (row<<8)|c0, or -1
__device__ int   g_owner[B_ * NZ_];                      // row -> owning d, or -1
__device__ int   g_fallback;

// ---------------------------------------------------------------------------
// Kernel 1: transpose x[b][ch*32+h][w] -> xT[b][w][ch*32+h]; block (0,0,0)
// also resets the owner table and fallback flag.
// ---------------------------------------------------------------------------
__global__ __launch_bounds__(256) void lss_transpose(const float* __restrict__ x) {
    __shared__ float tile[32][33];
    const int b  = blockIdx.z;
    const int r0 = blockIdx.x * 32;
    const int c0 = blockIdx.y * 32;
    const int tx = threadIdx.x;      // 0..31
    const int ty = threadIdx.y;      // 0..7
    const int tid = ty * 32 + tx;

    if (blockIdx.x == 0 && blockIdx.y == 0 && blockIdx.z == 0) {
        for (int i = tid; i < B_ * NZ_; i += 256) g_owner[i] = -1;
        if (tid == 0) g_fallback = 0;
    }

    const float* xb = x + (size_t)b * COLH * FW_;
#pragma unroll
    for (int i = ty; i < 32; i += 8) {
        int r = r0 + i, c = c0 + tx;
        if (c < FW_) tile[i][tx] = xb[(size_t)r * FW_ + c];
    }
    __syncthreads();
    float* xt = g_xT + (size_t)b * FW_ * COLH;
#pragma unroll
    for (int i = ty; i < 32; i += 8) {
        int w = c0 + i, r = r0 + tx;
        if (w < FW_) xt[(size_t)w * COLH + r] = tile[tx][i];
    }
}

// 3x3 inverse via adjugate, correctly-rounded divisions. Bit-sensitive; keep.
__device__ __forceinline__ void inv3(const float* m, float* o) {
    float a = m[0], b = m[1], c = m[2];
    float d = m[3], e = m[4], f = m[5];
    float g = m[6], h = m[7], i = m[8];
    float c00 = e * i - f * h;
    float c01 = f * g - d * i;
    float c02 = d * h - e * g;
    float det = a * c00 + b * c01 + c * c02;
    o[0] = __fdiv_rn(c00, det);
    o[1] = __fdiv_rn(c * h - b * i, det);
    o[2] = __fdiv_rn(b * f - c * e, det);
    o[3] = __fdiv_rn(c01, det);
    o[4] = __fdiv_rn(a * i - c * g, det);
    o[5] = __fdiv_rn(c * d - a * f, det);
    o[6] = __fdiv_rn(c02, det);
    o[7] = __fdiv_rn(b * g - a * h, det);
    o[8] = __fdiv_rn(a * e - b * d, det);
}

// Common softmax/geometry preamble used by both main_v and fallback.
// Fills wts[d][h] with normalized, mask-zeroed weights for d in [d0,d1).
// Returns per-warp bin info through out params (warp wg handles d=d0+wg step 8).
struct GeoOut { int d; int fl; int row; int c0; };

// ---------------------------------------------------------------------------
// Kernel 2: per-(w,b,z) compute V[d][c] = sum_h wts*feat, bins, owner claims.
// NO atomics on the output. 256 threads.
// ---------------------------------------------------------------------------
__global__ __launch_bounds__(256) void lss_main_v(
    const float* __restrict__ intrins,
    const float* __restrict__ rots,
    const float* __restrict__ trans)
{
    __shared__ float wts[DD][FH_];
    __shared__ float pmax[8][FH_];
    __shared__ float psum[8][FH_];
    __shared__ float fullmax[FH_];
    __shared__ float fsum[FH_];
    __shared__ float iR[9], iK[9], tv[3];

    const int w    = blockIdx.x;
    const int b    = blockIdx.y;
    const int z    = blockIdx.z;
    const int d0   = z * DCHUNK;
    const int d1   = (d0 + DCHUNK < DD) ? d0 + DCHUNK : DD;
    const int tid  = threadIdx.x;
    const int lane = tid & 31;
    const int wg   = tid >> 5;
    const int c    = ((wg & 1) << 5) + lane;
    const int dg   = wg >> 1;

    const float* xt = g_xT + ((size_t)b * FW_ + w) * COLH;

    // logits -> smem (contiguous float4)
    {
        const float4* src = (const float4*)xt;
        float4* dst = (float4*)&wts[0][0];
        for (int i = tid; i < (DD * FH_) / 4; i += 256) dst[i] = src[i];
    }
    // feature row for channel c -> registers (contiguous 128B per lane)
    float f[FH_];
    {
        const float4* xf = (const float4*)(xt + (size_t)(DD + c) * FH_);
#pragma unroll
        for (int k = 0; k < 8; k++) {
            float4 v = xf[k];
            f[4 * k + 0] = v.x; f[4 * k + 1] = v.y;
            f[4 * k + 2] = v.z; f[4 * k + 3] = v.w;
        }
    }
    if (tid == 0) {
        float mr[9], mk[9];
#pragma unroll
        for (int k = 0; k < 9; k++) { mr[k] = rots[b * 9 + k]; mk[k] = intrins[b * 9 + k]; }
        inv3(mr, iR);
        inv3(mk, iK);
        tv[0] = trans[b * 3 + 0]; tv[1] = trans[b * 3 + 1]; tv[2] = trans[b * 3 + 2];
    }
    __syncthreads();

    // softmax over all 41 d per h
    {
        float pm = -3.402823466e38f;
        for (int d = wg; d < DD; d += 8) pm = fmaxf(pm, wts[d][lane]);
        pmax[wg][lane] = pm;
    }
    __syncthreads();
    if (tid < 32) {
        float m = pmax[0][lane];
#pragma unroll
        for (int g = 1; g < 8; g++) m = fmaxf(m, pmax[g][lane]);
        fullmax[lane] = m;
    }
    __syncthreads();
    {
        float m = fullmax[lane];
        float ps = 0.f;
        for (int d = wg; d < DD; d += 8) {
            float e = __expf(wts[d][lane] - m);
            wts[d][lane] = e;
            ps += e;
        }
        psum[wg][lane] = ps;
    }
    __syncthreads();
    if (tid < 32) {
        float s = psum[0][lane];
#pragma unroll
        for (int g = 1; g < 8; g++) s += psum[g][lane];
        fsum[lane] = s;
    }
    __syncthreads();

    // geometry for this block's d-range; lane = h
    {
        const float xs = (float)w    * (703.0f / 87.0f);
        const float ys = (float)lane * (255.0f / 31.0f);
        const float r00 = iR[0], r01 = iR[1], r02 = iR[2];
        const float r10 = iR[3], r11 = iR[4], r12 = iR[5];
        const float r20 = iR[6], r21 = iR[7], r22 = iR[8];
        const float k00 = iK[0], k01 = iK[1], k02 = iK[2];
        const float k10 = iK[3], k11 = iK[4], k12 = iK[5];
        const float k20 = iK[6], k21 = iK[7], k22 = iK[8];
        const float t0 = tv[0], t1 = tv[1], t2 = tv[2];
        const float p0 = xs - t0, p1 = ys - t1;
        const float rinv = __frcp_rn(fsum[lane]);

        for (int d = d0 + wg; d < d1; d += 8) {
            float p2 = (4.0f + (float)d) - t2;
            float q0 = __fmaf_rn(r00, p0, __fmaf_rn(r01, p1, r02 * p2));
            float q1 = __fmaf_rn(r10, p0, __fmaf_rn(r11, p1, r12 * p2));
            float q2 = __fmaf_rn(r20, p0, __fmaf_rn(r21, p1, r22 * p2));
            float s0 = q0 * q2, s1 = q1 * q2, s2 = q2;
            float g0 = __fmaf_rn(k00, s0, __fmaf_rn(k01, s1, k02 * s2));
            float g1 = __fmaf_rn(k10, s0, __fmaf_rn(k11, s1, k12 * s2));
            float g2 = __fmaf_rn(k20, s0, __fmaf_rn(k21, s1, k22 * s2));
            int c0i = (int)((g0 + 50.0f) / 0.5f);
            int c1i = (int)((g1 + 10.0f) / 20.0f);
            int c2i = (int)(g2 / 0.25f);
            bool kept = (c0i >= 0) & (c0i < NX0_) & (c1i >= 0) & (c1i < 1) &
                        (c2i >= 0) & (c2i < NZ_);
            int sp = c2i * NX0_ + c0i;
            float wv = kept ? wts[d][lane] * rinv : 0.0f;
            wts[d][lane] = wv;

            unsigned km = __ballot_sync(0xffffffffu, kept);
            int pk = -1;
            if (km) {
                int src = __ffs(km) - 1;
                int lsp = __shfl_sync(0xffffffffu, sp, src);
                bool ok = (!kept) || (sp == lsp);
                if (__all_sync(0xffffffffu, ok)) {
                    int rr = lsp / NX0_, cc = lsp - rr * NX0_;
                    pk = (rr << 8) | cc;
                    if (lane == 0) {
                        int old = atomicCAS(&g_owner[b * NZ_ + rr], -1, d);
                        if (old != -1 && old != d) g_fallback = 1;
                    }
                } else {
                    if (lane == 0) g_fallback = 1;   // mixed bins within h
                }
            }
            if (lane == 0) g_bin[(b * DD + d) * FW_ + w] = pk;
        }
    }
    __syncthreads();

    // V[d][c] = sum_h wts[d][h]*f[h]; coalesced stores, no atomics
    {
        float* Vb = g_V + ((size_t)b * FW_ + w) * DD * CCH + c;
        for (int d = d0 + dg; d < d1; d += 4) {
            float a0 = 0.f, a1 = 0.f, a2 = 0.f, a3 = 0.f;
#pragma unroll
            for (int h = 0; h < FH_; h += 4) {
                a0 = __fmaf_rn(wts[d][h + 0], f[h + 0], a0);
                a1 = __fmaf_rn(wts[d][h + 1], f[h + 1], a1);
                a2 = __fmaf_rn(wts[d][h + 2], f[h + 2], a2);
                a3 = __fmaf_rn(wts[d][h + 3], f[h + 3], a3);
            }
            Vb[(size_t)d * CCH] = (a0 + a1) + (a2 + a3);
        }
    }
}

// ---------------------------------------------------------------------------
// Kernel 3: writer. Block (quarter, row, b). Writes every output byte exactly
// once (doubles as the zero-fill). Owned rows gather V over w via smem.
// ---------------------------------------------------------------------------
__global__ __launch_bounds__(256) void lss_writer(float* __restrict__ out) {
    __shared__ float acc[CCH][51];   // [c][c0local], padded to kill conflicts
    const int q   = blockIdx.x;      // 0..3
    const int r   = blockIdx.y;      // 0..199
    const int b   = blockIdx.z;
    const int tid = threadIdx.x;
    const int q0  = q * 50;

    const int d  = g_owner[b * NZ_ + r];
    const bool fb = (g_fallback != 0);

    if (d >= 0 && !fb) {
        for (int i = tid; i < CCH * 51; i += 256) ((float*)acc)[i] = 0.f;
        __syncthreads();
        const int c   = tid & 63;
        const int wgp = tid >> 6;
        const int binbase = (b * DD + d) * FW_;
        const float* Vb = g_V + ((size_t)b * FW_ * DD + d) * CCH + c;
        for (int w = wgp; w < FW_; w += 4) {
            int pk = g_bin[binbase + w];
            if (pk < 0) continue;
            int row = pk >> 8;
            if (row != r) continue;
            int c0l = (pk & 255) - q0;
            if ((unsigned)c0l >= 50u) continue;
            atomicAdd(&acc[c][c0l], Vb[(size_t)w * DD * CCH]);
        }
        __syncthreads();
        for (int i = tid; i < CCH * 25; i += 256) {
            int cc = i / 25, j = (i % 25) * 2;
            float2 v2 = make_float2(acc[cc][j], acc[cc][j + 1]);
            *(float2*)(out + (((size_t)(b * CCH + cc) * NZ_ + r) * NX0_ + q0 + j)) = v2;
        }
    } else {
        const float2 z2 = make_float2(0.f, 0.f);
        for (int i = tid; i < CCH * 25; i += 256) {
            int cc = i / 25, j = (i % 25) * 2;
            *(float2*)(out + (((size_t)(b * CCH + cc) * NZ_ + r) * NX0_ + q0 + j)) = z2;
        }
    }
}

// ---------------------------------------------------------------------------
// Kernel 4: generic fallback (R4's proven atomic path). Early-exits unless
// the structure checks failed. Writer has already zero-filled out.
// ---------------------------------------------------------------------------
__global__ __launch_bounds__(256) void lss_fallback(
    const float* __restrict__ intrins,
    const float* __restrict__ rots,
    const float* __restrict__ trans,
    float* __restrict__ out)
{
    if (g_fallback == 0) return;

    __shared__ float wts[DD][FH_];
    __shared__ float pmax[8][FH_];
    __shared__ float psum[8][FH_];
    __shared__ float fullmax[FH_];
    __shared__ float fsum[FH_];
    __shared__ int   binh[DD][FH_];
    __shared__ float iR[9], iK[9], tv[3];

    const int w    = blockIdx.x;
    const int b    = blockIdx.y;
    const int tid  = threadIdx.x;
    const int lane = tid & 31;
    const int wg   = tid >> 5;
    const int c    = ((wg & 1) << 5) + lane;
    const int dg   = wg >> 1;

    const float* xt = g_xT + ((size_t)b * FW_ + w) * COLH;
    {
        const float4* src = (const float4*)xt;
        float4* dst = (float4*)&wts[0][0];
        for (int i = tid; i < (DD * FH_) / 4; i += 256) dst[i] = src[i];
    }
    float f[FH_];
    {
        const float4* xf = (const float4*)(xt + (size_t)(DD + c) * FH_);
#pragma unroll
        for (int k = 0; k < 8; k++) {
            float4 v = xf[k];
            f[4 * k + 0] = v.x; f[4 * k + 1] = v.y;
            f[4 * k + 2] = v.z; f[4 * k + 3] = v.w;
        }
    }
    if (tid == 0) {
        float mr[9], mk[9];
#pragma unroll
        for (int k = 0; k < 9; k++) { mr[k] = rots[b * 9 + k]; mk[k] = intrins[b * 9 + k]; }
        inv3(mr, iR);
        inv3(mk, iK);
        tv[0] = trans[b * 3 + 0]; tv[1] = trans[b * 3 + 1]; tv[2] = trans[b * 3 + 2];
    }
    __syncthreads();
    {
        float pm = -3.402823466e38f;
        for (int d = wg; d < DD; d += 8) pm = fmaxf(pm, wts[d][lane]);
        pmax[wg][lane] = pm;
    }
    __syncthreads();
    if (tid < 32) {
        float m = pmax[0][lane];
#pragma unroll
        for (int g = 1; g < 8; g++) m = fmaxf(m, pmax[g][lane]);
        fullmax[lane] = m;
    }
    __syncthreads();
    {
        float m = fullmax[lane];
        float ps = 0.f;
        for (int d = wg; d < DD; d += 8) {
            float e = __expf(wts[d][lane] - m);
            wts[d][lane] = e;
            ps += e;
        }
        psum[wg][lane] = ps;
    }
    __syncthreads();
    if (tid < 32) {
        float s = psum[0][lane];
#pragma unroll
        for (int g = 1; g < 8; g++) s += psum[g][lane];
        fsum[lane] = s;
    }
    __syncthreads();
    {
        const float xs = (float)w    * (703.0f / 87.0f);
        const float ys = (float)lane * (255.0f / 31.0f);
        const float t0 = tv[0], t1 = tv[1], t2 = tv[2];
        const float p0 = xs - t0, p1 = ys - t1;
        const float rinv = __frcp_rn(fsum[lane]);
        for (int d = wg; d < DD; d += 8) {
            float p2 = (4.0f + (float)d) - t2;
            float q0 = __fmaf_rn(iR[0], p0, __fmaf_rn(iR[1], p1, iR[2] * p2));
            float q1 = __fmaf_rn(iR[3], p0, __fmaf_rn(iR[4], p1, iR[5] * p2));
            float q2 = __fmaf_rn(iR[6], p0, __fmaf_rn(iR[7], p1, iR[8] * p2));
            float s0 = q0 * q2, s1 = q1 * q2, s2 = q2;
            float g0 = __fmaf_rn(iK[0], s0, __fmaf_rn(iK[1], s1, iK[2] * s2));
            float g1 = __fmaf_rn(iK[3], s0, __fmaf_rn(iK[4], s1, iK[5] * s2));
            float g2 = __fmaf_rn(iK[6], s0, __fmaf_rn(iK[7], s1, iK[8] * s2));
            int c0i = (int)((g0 + 50.0f) / 0.5f);
            int c1i = (int)((g1 + 10.0f) / 20.0f);
            int c2i = (int)(g2 / 0.25f);
            bool kept = (c0i >= 0) & (c0i < NX0_) & (c1i >= 0) & (c1i < 1) &
                        (c2i >= 0) & (c2i < NZ_);
            binh[d][lane] = c2i * NX0_ + c0i;
            wts[d][lane] = kept ? wts[d][lane] * rinv : 0.0f;
        }
    }
    __syncthreads();
    {
        float* ob = out + ((size_t)b * CCH + c) * (NZ_ * NX0_);
        for (int d = dg; d < DD; d += 4) {
#pragma unroll
            for (int h = 0; h < FH_; h++) {
                float wv = wts[d][h];
                if (wv != 0.f) atomicAdd(ob + binh[d][h], wv * f[h]);
            }
        }
    }
}

// ---------------------------------------------------------------------------
extern "C" void kernel_launch(void* const* d_in, const int* in_sizes, int n_in,
                              void* d_out, int out_size) {
    const float* x       = (const float*)d_in[0];
    const float* intrins = (const float*)d_in[1];
    const float* rots    = (const float*)d_in[2];
    const float* trans   = (const float*)d_in[3];
    float* out = (float*)d_out;

    dim3 tgrid(COLH / 32, (FW_ + 31) / 32, B_);
    lss_transpose<<<tgrid, dim3(32, 8)>>>(x);

    dim3 vgrid(FW_, B_, DSPLIT);
    lss_main_v<<<vgrid, 256>>>(intrins, rots, trans);

    dim3 wgrid(4, NZ_, B_);
    lss_writer<<<wgrid, 256>>>(out);

    dim3 fgrid(FW_, B_);
    lss_fallback<<<fgrid, 256>>>(intrins, rots, trans, out);
}

// round 6
// speedup vs baseline: 1.3149x; 1.3149x over previous
#include <cuda_runtime.h>
#include <cstdint>

// Problem constants (from reference)
#define DD   41
#define CCH  64
#define CHT  105          // DD + CCH
#define FH_  32
#define FW_  88
#define B_   4
#define NX0_ 200
#define NZ_  200
#define COLH (CHT * FH_)  // 3360 floats per (b,w) column in xT
#define DSPLIT 2
#define DCHUNK 21         // ceil(41/2)
#define OUTN  (B_ * CCH * NZ_ * NX0_)   // 10,240,000 floats

// Static scratch: x transposed to [b][w][ch][h] (4.73 MB)
__device__ float g_xT[(size_t)B_ * FW_ * COLH];

// ---------------------------------------------------------------------------
// Kernel 1: fused (a) zero-fill of out (replaces cudaMemset) and
//           (b) transpose x[b][ch*32+h][w] -> xT[b][w][ch*32+h].
// grid (105, 3, 4) x 256 thr. Zero stores are fire-and-forget STG.128.
// ---------------------------------------------------------------------------
__global__ __launch_bounds__(256) void lss_prep(const float* __restrict__ x,
                                                float* __restrict__ out) {
    __shared__ float tile[32][33];
    const int tx  = threadIdx.x & 31;
    const int ty  = threadIdx.x >> 5;          // 0..7
    const int tid = threadIdx.x;

    // (a) zero my slice of out (float4, grid-strided)
    {
        const int nblk = gridDim.x * gridDim.y * gridDim.z;          // 1260
        const int lin  = (blockIdx.z * gridDim.y + blockIdx.y) * gridDim.x
                       + blockIdx.x;
        float4* o4 = (float4*)out;
        const int n4 = OUTN / 4;                                     // 2,560,000
        const float4 z4 = make_float4(0.f, 0.f, 0.f, 0.f);
        for (int i = lin * 256 + tid; i < n4; i += nblk * 256) o4[i] = z4;
    }

    // (b) 32x32 tile transpose
    const int b  = blockIdx.z;
    const int r0 = blockIdx.x * 32;   // row = ch*32+h (0..3359)
    const int c0 = blockIdx.y * 32;   // col = w       (0..87)

    const float* xb = x + (size_t)b * COLH * FW_;
#pragma unroll
    for (int i = ty; i < 32; i += 8) {
        int r = r0 + i, c = c0 + tx;
        if (c < FW_) tile[i][tx] = xb[(size_t)r * FW_ + c];
    }
    __syncthreads();
    float* xt = g_xT + (size_t)b * FW_ * COLH;
#pragma unroll
    for (int i = ty; i < 32; i += 8) {
        int w = c0 + i, r = r0 + tx;
        if (w < FW_) xt[(size_t)w * COLH + r] = tile[tx][i];
    }
}

// 3x3 inverse via adjugate, correctly-rounded divisions. Bit-sensitive; keep.
__device__ __forceinline__ void inv3(const float* m, float* o) {
    float a = m[0], b = m[1], c = m[2];
    float d = m[3], e = m[4], f = m[5];
    float g = m[6], h = m[7], i = m[8];
    float c00 = e * i - f * h;
    float c01 = f * g - d * i;
    float c02 = d * h - e * g;
    float det = a * c00 + b * c01 + c * c02;
    o[0] = __fdiv_rn(c00, det);
    o[1] = __fdiv_rn(c * h - b * i, det);
    o[2] = __fdiv_rn(b * f - c * e, det);
    o[3] = __fdiv_rn(c01, det);
    o[4] = __fdiv_rn(a * i - c * g, det);
    o[5] = __fdiv_rn(c * d - a * f, det);
    o[6] = __fdiv_rn(c02, det);
    o[7] = __fdiv_rn(b * g - a * h, det);
    o[8] = __fdiv_rn(a * e - b * d, det);
}

// ---------------------------------------------------------------------------
// Kernel 2: main. One block per (w, b, d-half). 256 threads = 8 warps.
// Phases 1-2 (softmax) over all 41 d; phases 3-4 over this block's d-range.
// Phase 4: ONE atomic per (d, channel) on the uniform path (proven R4 logic).
// ---------------------------------------------------------------------------
__global__ __launch_bounds__(256) void lss_main(
    const float* __restrict__ intrins,
    const float* __restrict__ rots,
    const float* __restrict__ trans,
    float* __restrict__ out)
{
    __shared__ float wts[DD][FH_];      // logits -> exp -> masked weights
    __shared__ float pmax[8][FH_];
    __shared__ float psum[8][FH_];
    __shared__ float fullmax[FH_];
    __shared__ float fsum[FH_];
    __shared__ int   binsp[DD];
    __shared__ int   flags[DD];         // 0 = no kept, 1 = uniform, 2 = mixed
    __shared__ int   binh[DD][FH_];
    __shared__ float iR[9], iK[9], tv[3];

    const int w    = blockIdx.x;
    const int b    = blockIdx.y;
    const int d0   = blockIdx.z * DCHUNK;
    const int d1   = (d0 + DCHUNK < DD) ? d0 + DCHUNK : DD;
    const int tid  = threadIdx.x;
    const int lane = tid & 31;
    const int wg   = tid >> 5;                 // 0..7
    const int c    = ((wg & 1) << 5) + lane;   // phase-4 channel
    const int dg   = wg >> 1;                  // phase-4 d-subgroup (0..3)

    const float* xt = g_xT + ((size_t)b * FW_ + w) * COLH;

    // Phase 1a: logits 41x32 (contiguous) -> smem via float4
    {
        const float4* src = (const float4*)xt;
        float4* dst = (float4*)&wts[0][0];
        for (int i = tid; i < (DD * FH_) / 4; i += 256) dst[i] = src[i];
    }
    if (tid == 0) {
        float mr[9], mk[9];
#pragma unroll
        for (int k = 0; k < 9; k++) { mr[k] = rots[b * 9 + k]; mk[k] = intrins[b * 9 + k]; }
        inv3(mr, iR);
        inv3(mk, iK);
        tv[0] = trans[b * 3 + 0]; tv[1] = trans[b * 3 + 1]; tv[2] = trans[b * 3 + 2];
    }
    __syncthreads();

    // Phase 2: softmax over all 41 d per h (needed for normalization)
    {
        float pm = -3.402823466e38f;
        for (int d = wg; d < DD; d += 8) pm = fmaxf(pm, wts[d][lane]);
        pmax[wg][lane] = pm;
    }
    __syncthreads();
    if (tid < 32) {
        float m = pmax[0][lane];
#pragma unroll
        for (int g = 1; g < 8; g++) m = fmaxf(m, pmax[g][lane]);
        fullmax[lane] = m;
    }
    __syncthreads();
    {
        float m = fullmax[lane];
        float ps = 0.f;
        for (int d = wg; d < DD; d += 8) {
            float e = __expf(wts[d][lane] - m);
            wts[d][lane] = e;
            ps += e;
        }
        psum[wg][lane] = ps;
    }
    __syncthreads();
    if (tid < 32) {
        float s = psum[0][lane];
#pragma unroll
        for (int g = 1; g < 8; g++) s += psum[g][lane];
        fsum[lane] = s;
    }
    __syncthreads();

    // Phase 3: geometry for this block's d-range; lane = h.
    {
        const float xs = (float)w    * (703.0f / 87.0f);
        const float ys = (float)lane * (255.0f / 31.0f);
        const float r00 = iR[0], r01 = iR[1], r02 = iR[2];
        const float r10 = iR[3], r11 = iR[4], r12 = iR[5];
        const float r20 = iR[6], r21 = iR[7], r22 = iR[8];
        const float k00 = iK[0], k01 = iK[1], k02 = iK[2];
        const float k10 = iK[3], k11 = iK[4], k12 = iK[5];
        const float k20 = iK[6], k21 = iK[7], k22 = iK[8];
        const float t0 = tv[0], t1 = tv[1], t2 = tv[2];
        const float p0 = xs - t0, p1 = ys - t1;
        const float rinv = __frcp_rn(fsum[lane]);

        for (int d = d0 + wg; d < d1; d += 8) {
            float p2 = (4.0f + (float)d) - t2;
            float q0 = __fmaf_rn(r00, p0, __fmaf_rn(r01, p1, r02 * p2));
            float q1 = __fmaf_rn(r10, p0, __fmaf_rn(r11, p1, r12 * p2));
            float q2 = __fmaf_rn(r20, p0, __fmaf_rn(r21, p1, r22 * p2));
            float s0 = q0 * q2, s1 = q1 * q2, s2 = q2;
            float g0 = __fmaf_rn(k00, s0, __fmaf_rn(k01, s1, k02 * s2));
            float g1 = __fmaf_rn(k10, s0, __fmaf_rn(k11, s1, k12 * s2));
            float g2 = __fmaf_rn(k20, s0, __fmaf_rn(k21, s1, k22 * s2));
            // truncation toward zero matches astype(int32)
            int c0i = (int)((g0 + 50.0f) / 0.5f);
            int c1i = (int)((g1 + 10.0f) / 20.0f);
            int c2i = (int)(g2 / 0.25f);
            bool kept = (c0i >= 0) & (c0i < NX0_) & (c1i >= 0) & (c1i < 1) &
                        (c2i >= 0) & (c2i < NZ_);
            int sp = c2i * NX0_ + c0i;
            binh[d][lane] = sp;
            float wv = kept ? wts[d][lane] * rinv : 0.0f;
            wts[d][lane] = wv;

            unsigned km = __ballot_sync(0xffffffffu, kept);
            int fl = 0;
            if (km) {
                int src = __ffs(km) - 1;
                int lsp = __shfl_sync(0xffffffffu, sp, src);
                bool ok = (!kept) || (sp == lsp);
                fl = __all_sync(0xffffffffu, ok) ? 1 : 2;
                if (lane == 0) binsp[d] = lsp;
            }
            if (lane == 0) flags[d] = fl;
        }
    }
    __syncthreads();

    // Phase 4: load feature row for channel c NOW (low live range earlier),
    // then matvec + scatter. wts reads are warp-broadcast LDS; f in regs.
    {
        float f[FH_];
        const float4* xf = (const float4*)(xt + (size_t)(DD + c) * FH_);
#pragma unroll
        for (int k = 0; k < 8; k++) {
            float4 v = xf[k];
            f[4 * k + 0] = v.x; f[4 * k + 1] = v.y;
            f[4 * k + 2] = v.z; f[4 * k + 3] = v.w;
        }

        float* ob = out + ((size_t)b * CCH + c) * (NZ_ * NX0_);
        for (int d = d0 + dg; d < d1; d += 4) {
            int fl = flags[d];
            if (fl == 0) continue;
            if (fl == 1) {
                float a0 = 0.f, a1 = 0.f, a2 = 0.f, a3 = 0.f;
#pragma unroll
                for (int h = 0; h < FH_; h += 4) {
                    a0 = __fmaf_rn(wts[d][h + 0], f[h + 0], a0);
                    a1 = __fmaf_rn(wts[d][h + 1], f[h + 1], a1);
                    a2 = __fmaf_rn(wts[d][h + 2], f[h + 2], a2);
                    a3 = __fmaf_rn(wts[d][h + 3], f[h + 3], a3);
                }
                atomicAdd(ob + binsp[d], (a0 + a1) + (a2 + a3));
            } else {
                // generic fallback: per-h scatter (unrolled so f stays in regs)
#pragma unroll
                for (int h = 0; h < FH_; h++) {
                    float wv = wts[d][h];
                    if (wv != 0.f) atomicAdd(ob + binh[d][h], wv * f[h]);
                }
            }
        }
    }
}

// ---------------------------------------------------------------------------
extern "C" void kernel_launch(void* const* d_in, const int* in_sizes, int n_in,
                              void* d_out, int out_size) {
    const float* x       = (const float*)d_in[0];
    const float* intrins = (const float*)d_in[1];
    const float* rots    = (const float*)d_in[2];
    const float* trans   = (const float*)d_in[3];
    float* out = (float*)d_out;

    // fused zero-fill + transpose
    dim3 pgrid(COLH / 32, (FW_ + 31) / 32, B_);   // (105, 3, 4)
    lss_prep<<<pgrid, 256>>>(x, out);

    // main: d-split doubles grid for latency hiding
    dim3 mgrid(FW_, B_, DSPLIT);
    lss_main<<<mgrid, 256>>>(intrins, rots, trans, out);
}

// round 7
// speedup vs baseline: 1.3950x; 1.0609x over previous
#include <cuda_runtime.h>
#include <cstdint>

// Problem constants (from reference)
#define DD   41
#define CCH  64
#define CHT  105          // DD + CCH
#define FH_  32
#define FW_  88
#define B_   4
#define NX0_ 200
#define NZ_  200
#define COLH (CHT * FH_)  // 3360 floats per (b,w) column in xT
#define OUTN  (B_ * CCH * NZ_ * NX0_)   // 10,240,000 floats

#define LPAD 43           // lgT row pitch (odd => conflict-free both ways)
#define FPAD 36           // sf row pitch (16B aligned, 9c+k mod 32 distinct)

// Static scratch: x transposed to [b][w][ch][h] (4.73 MB)
__device__ float g_xT[(size_t)B_ * FW_ * COLH];

// ---------------------------------------------------------------------------
// Kernel 1: fused (a) zero-fill of out and (b) transpose
// x[b][ch*32+h][w] -> xT[b][w][ch*32+h].  grid (105, 3, 4) x 256 thr.
// ---------------------------------------------------------------------------
__global__ __launch_bounds__(256) void lss_prep(const float* __restrict__ x,
                                                float* __restrict__ out) {
    __shared__ float tile[32][33];
    const int tx  = threadIdx.x & 31;
    const int ty  = threadIdx.x >> 5;
    const int tid = threadIdx.x;

    // (a) zero my slice of out (float4, grid-strided)
    {
        const int nblk = gridDim.x * gridDim.y * gridDim.z;
        const int lin  = (blockIdx.z * gridDim.y + blockIdx.y) * gridDim.x
                       + blockIdx.x;
        float4* o4 = (float4*)out;
        const int n4 = OUTN / 4;
        const float4 z4 = make_float4(0.f, 0.f, 0.f, 0.f);
        for (int i = lin * 256 + tid; i < n4; i += nblk * 256) o4[i] = z4;
    }

    // (b) 32x32 tile transpose
    const int b  = blockIdx.z;
    const int r0 = blockIdx.x * 32;
    const int c0 = blockIdx.y * 32;

    const float* xb = x + (size_t)b * COLH * FW_;
#pragma unroll
    for (int i = ty; i < 32; i += 8) {
        int r = r0 + i, c = c0 + tx;
        if (c < FW_) tile[i][tx] = xb[(size_t)r * FW_ + c];
    }
    __syncthreads();
    float* xt = g_xT + (size_t)b * FW_ * COLH;
#pragma unroll
    for (int i = ty; i < 32; i += 8) {
        int w = c0 + i, r = r0 + tx;
        if (w < FW_) xt[(size_t)w * COLH + r] = tile[tx][i];
    }
}

// 3x3 inverse via adjugate, correctly-rounded divisions. Bit-sensitive; keep.
__device__ __forceinline__ void inv3(const float* m, float* o) {
    float a = m[0], b = m[1], c = m[2];
    float d = m[3], e = m[4], f = m[5];
    float g = m[6], h = m[7], i = m[8];
    float c00 = e * i - f * h;
    float c01 = f * g - d * i;
    float c02 = d * h - e * g;
    float det = a * c00 + b * c01 + c * c02;
    o[0] = __fdiv_rn(c00, det);
    o[1] = __fdiv_rn(c * h - b * i, det);
    o[2] = __fdiv_rn(b * f - c * e, det);
    o[3] = __fdiv_rn(c01, det);
    o[4] = __fdiv_rn(a * i - c * g, det);
    o[5] = __fdiv_rn(c * d - a * f, det);
    o[6] = __fdiv_rn(c02, det);
    o[7] = __fdiv_rn(b * g - a * h, det);
    o[8] = __fdiv_rn(a * e - b * d, det);
}

__device__ __forceinline__ float warp_max(float v) {
#pragma unroll
    for (int off = 16; off > 0; off >>= 1)
        v = fmaxf(v, __shfl_xor_sync(0xffffffffu, v, off));
    return v;
}
__device__ __forceinline__ float warp_sum(float v) {
#pragma unroll
    for (int off = 16; off > 0; off >>= 1)
        v += __shfl_xor_sync(0xffffffffu, v, off);
    return v;
}

// ---------------------------------------------------------------------------
// Kernel 2: main. One block per (w, b). 512 threads = 16 warps.
//  P1: logits -> lgT[h][d] (transposed, padded); features -> sf[c][h] (coop,
//      coalesced global reads)
//  P2: softmax per h, warp-local (lane = d, shuffle reductions, no barriers)
//  P3: geometry per (d,h), lane = h; h-uniformity ballot; normalize+mask wts
//  P4: warp = (dg 0..7, chalf), lane -> channel; f from sf via LDS.128;
//      ONE atomic per (d, channel) on the uniform path.
// ---------------------------------------------------------------------------
__global__ __launch_bounds__(512) void lss_main(
    const float* __restrict__ intrins,
    const float* __restrict__ rots,
    const float* __restrict__ trans,
    float* __restrict__ out)
{
    __shared__ float lgT[FH_][LPAD];    // [h][d]: logits -> exp -> weights
    __shared__ float sf[CCH][FPAD];     // [c][h]: feature stage
    __shared__ float rinvS[FH_];        // per-h 1/sum
    __shared__ int   binsp[DD];
    __shared__ int   flags[DD];         // 0 = no kept, 1 = uniform, 2 = mixed
    __shared__ int   binh[DD][FH_];
    __shared__ float iR[9], iK[9], tv[3];

    const int w    = blockIdx.x;
    const int b    = blockIdx.y;
    const int tid  = threadIdx.x;
    const int lane = tid & 31;
    const int wg   = tid >> 5;                 // 0..15

    const float* xt = g_xT + ((size_t)b * FW_ + w) * COLH;

    // P1a: logits 41x32 -> lgT transposed. float4 i covers (d=i>>3, 4 h's).
    {
        const float4* src = (const float4*)xt;
        for (int i = tid; i < (DD * FH_) / 4; i += 512) {
            float4 v = src[i];
            int d = i >> 3, h4 = (i & 7) << 2;
            lgT[h4 + 0][d] = v.x;
            lgT[h4 + 1][d] = v.y;
            lgT[h4 + 2][d] = v.z;
            lgT[h4 + 3][d] = v.w;
        }
    }
    // P1b: features 64x32 -> sf[c][h] (global side contiguous float4)
    {
        const float4* src = (const float4*)(xt + DD * FH_);
        for (int i = tid; i < (CCH * FH_) / 4; i += 512) {
            float4 v = src[i];
            int c = i >> 3, h4 = (i & 7) << 2;
            float* p = &sf[c][h4];
            p[0] = v.x; p[1] = v.y; p[2] = v.z; p[3] = v.w;
        }
    }
    if (tid == 0) {
        float mr[9], mk[9];
#pragma unroll
        for (int k = 0; k < 9; k++) { mr[k] = rots[b * 9 + k]; mk[k] = intrins[b * 9 + k]; }
        inv3(mr, iR);
        inv3(mk, iK);
        tv[0] = trans[b * 3 + 0]; tv[1] = trans[b * 3 + 1]; tv[2] = trans[b * 3 + 2];
    }
    __syncthreads();

    // P2: softmax per h; warp wg owns h = 2wg, 2wg+1; lane = d (and d+32).
#pragma unroll
    for (int k = 0; k < 2; k++) {
        int h = 2 * wg + k;
        float v0 = lgT[h][lane];
        float v1 = (lane < DD - 32) ? lgT[h][lane + 32] : -3.402823466e38f;
        float m = warp_max(fmaxf(v0, v1));
        float e0 = __expf(v0 - m);
        float e1 = (lane < DD - 32) ? __expf(v1 - m) : 0.f;
        float s = warp_sum(e0 + e1);
        lgT[h][lane] = e0;
        if (lane < DD - 32) lgT[h][lane + 32] = e1;
        if (lane == 0) rinvS[h] = __frcp_rn(s);
    }
    __syncthreads();

    // P3: geometry. warp wg handles d = wg, wg+16, wg+32; lane = h.
    {
        const float xs = (float)w    * (703.0f / 87.0f);
        const float ys = (float)lane * (255.0f / 31.0f);
        const float r00 = iR[0], r01 = iR[1], r02 = iR[2];
        const float r10 = iR[3], r11 = iR[4], r12 = iR[5];
        const float r20 = iR[6], r21 = iR[7], r22 = iR[8];
        const float k00 = iK[0], k01 = iK[1], k02 = iK[2];
        const float k10 = iK[3], k11 = iK[4], k12 = iK[5];
        const float k20 = iK[6], k21 = iK[7], k22 = iK[8];
        const float t0 = tv[0], t1 = tv[1], t2 = tv[2];
        const float p0 = xs - t0, p1 = ys - t1;
        const float rinv = rinvS[lane];

        for (int d = wg; d < DD; d += 16) {
            float p2 = (4.0f + (float)d) - t2;
            float q0 = __fmaf_rn(r00, p0, __fmaf_rn(r01, p1, r02 * p2));
            float q1 = __fmaf_rn(r10, p0, __fmaf_rn(r11, p1, r12 * p2));
            float q2 = __fmaf_rn(r20, p0, __fmaf_rn(r21, p1, r22 * p2));
            float s0 = q0 * q2, s1 = q1 * q2, s2 = q2;
            float g0 = __fmaf_rn(k00, s0, __fmaf_rn(k01, s1, k02 * s2));
            float g1 = __fmaf_rn(k10, s0, __fmaf_rn(k11, s1, k12 * s2));
            float g2 = __fmaf_rn(k20, s0, __fmaf_rn(k21, s1, k22 * s2));
            // truncation toward zero matches astype(int32)
            int c0i = (int)((g0 + 50.0f) / 0.5f);
            int c1i = (int)((g1 + 10.0f) / 20.0f);
            int c2i = (int)(g2 / 0.25f);
            bool kept = (c0i >= 0) & (c0i < NX0_) & (c1i >= 0) & (c1i < 1) &
                        (c2i >= 0) & (c2i < NZ_);
            int sp = c2i * NX0_ + c0i;
            binh[d][lane] = sp;
            float wv = kept ? lgT[lane][d] * rinv : 0.0f;
            lgT[lane][d] = wv;

            unsigned km = __ballot_sync(0xffffffffu, kept);
            int fl = 0;
            if (km) {
                int src = __ffs(km) - 1;
                int lsp = __shfl_sync(0xffffffffu, sp, src);
                bool ok = (!kept) || (sp == lsp);
                fl = __all_sync(0xffffffffu, ok) ? 1 : 2;
                if (lane == 0) binsp[d] = lsp;
            }
            if (lane == 0) flags[d] = fl;
        }
    }
    __syncthreads();

    // P4: matvec + scatter. warp wg: chalf = wg&1, dg = wg>>1 (0..7);
    // lane owns channel c = chalf*32 + lane. f via conflict-free LDS.128.
    {
        const int c  = ((wg & 1) << 5) + lane;
        const int dg = wg >> 1;

        float f[FH_];
        {
            const float4* sfc = (const float4*)&sf[c][0];
#pragma unroll
            for (int k = 0; k < 8; k++) {
                float4 v = sfc[k];
                f[4 * k + 0] = v.x; f[4 * k + 1] = v.y;
                f[4 * k + 2] = v.z; f[4 * k + 3] = v.w;
            }
        }

        float* ob = out + ((size_t)b * CCH + c) * (NZ_ * NX0_);
        for (int d = dg; d < DD; d += 8) {
            int fl = flags[d];
            if (fl == 0) continue;
            if (fl == 1) {
                float a0 = 0.f, a1 = 0.f, a2 = 0.f, a3 = 0.f;
#pragma unroll
                for (int h = 0; h < FH_; h += 4) {
                    a0 = __fmaf_rn(lgT[h + 0][d], f[h + 0], a0);
                    a1 = __fmaf_rn(lgT[h + 1][d], f[h + 1], a1);
                    a2 = __fmaf_rn(lgT[h + 2][d], f[h + 2], a2);
                    a3 = __fmaf_rn(lgT[h + 3][d], f[h + 3], a3);
                }
                atomicAdd(ob + binsp[d], (a0 + a1) + (a2 + a3));
            } else {
                // generic fallback: per-h scatter
#pragma unroll
                for (int h = 0; h < FH_; h++) {
                    float wv = lgT[h][d];
                    if (wv != 0.f) atomicAdd(ob + binh[d][h], wv * f[h]);
                }
            }
        }
    }
}

// ---------------------------------------------------------------------------
extern "C" void kernel_launch(void* const* d_in, const int* in_sizes, int n_in,
                              void* d_out, int out_size) {
    const float* x       = (const float*)d_in[0];
    const float* intrins = (const float*)d_in[1];
    const float* rots    = (const float*)d_in[2];
    const float* trans   = (const float*)d_in[3];
    float* out = (float*)d_out;

    // fused zero-fill + transpose
    dim3 pgrid(COLH / 32, (FW_ + 31) / 32, B_);   // (105, 3, 4)
    lss_prep<<<pgrid, 256>>>(x, out);

    dim3 mgrid(FW_, B_);
    lss_main<<<mgrid, 512>>>(intrins, rots, trans, out);
}

// round 8
// speedup vs baseline: 1.6373x; 1.1737x over previous
#include <cuda_runtime.h>
#include <cstdint>

// Problem constants (from reference)
#define DD   41
#define CCH  64
#define CHT  105          // DD + CCH
#define FH_  32
#define FW_  88
#define B_   4
#define NX0_ 200
#define NZ_  200
#define COLH (CHT * FH_)  // 3360 floats per (b,w) column in xT
#define OUTN  (B_ * CCH * NZ_ * NX0_)   // 10,240,000 floats
#define FPAD 36           // sf pitch: 16B-aligned rows, conflict-free LDS.128

// Static scratch: x transposed to [b][w][ch][h] (4.73 MB)
__device__ float g_xT[(size_t)B_ * FW_ * COLH];

// ---------------------------------------------------------------------------
// Kernel 1: fused (a) zero-fill of out and (b) transpose
// x[b][ch*32+h][w] -> xT[b][w][ch*32+h].  grid (105, 3, 4) x 256 thr.
// ---------------------------------------------------------------------------
__global__ __launch_bounds__(256) void lss_prep(const float* __restrict__ x,
                                                float* __restrict__ out) {
    __shared__ float tile[32][33];
    const int tx  = threadIdx.x & 31;
    const int ty  = threadIdx.x >> 5;
    const int tid = threadIdx.x;

    // (a) zero my slice of out (float4, grid-strided)
    {
        const int nblk = gridDim.x * gridDim.y * gridDim.z;
        const int lin  = (blockIdx.z * gridDim.y + blockIdx.y) * gridDim.x
                       + blockIdx.x;
        float4* o4 = (float4*)out;
        const int n4 = OUTN / 4;
        const float4 z4 = make_float4(0.f, 0.f, 0.f, 0.f);
        for (int i = lin * 256 + tid; i < n4; i += nblk * 256) o4[i] = z4;
    }

    // (b) 32x32 tile transpose
    const int b  = blockIdx.z;
    const int r0 = blockIdx.x * 32;
    const int c0 = blockIdx.y * 32;

    const float* xb = x + (size_t)b * COLH * FW_;
#pragma unroll
    for (int i = ty; i < 32; i += 8) {
        int r = r0 + i, c = c0 + tx;
        if (c < FW_) tile[i][tx] = xb[(size_t)r * FW_ + c];
    }
    __syncthreads();
    float* xt = g_xT + (size_t)b * FW_ * COLH;
#pragma unroll
    for (int i = ty; i < 32; i += 8) {
        int w = c0 + i, r = r0 + tx;
        if (w < FW_) xt[(size_t)w * COLH + r] = tile[tx][i];
    }
}

// 3x3 inverse via adjugate, correctly-rounded divisions. Bit-sensitive; keep.
__device__ __forceinline__ void inv3(const float* m, float* o) {
    float a = m[0], b = m[1], c = m[2];
    float d = m[3], e = m[4], f = m[5];
    float g = m[6], h = m[7], i = m[8];
    float c00 = e * i - f * h;
    float c01 = f * g - d * i;
    float c02 = d * h - e * g;
    float det = a * c00 + b * c01 + c * c02;
    o[0] = __fdiv_rn(c00, det);
    o[1] = __fdiv_rn(c * h - b * i, det);
    o[2] = __fdiv_rn(b * f - c * e, det);
    o[3] = __fdiv_rn(c01, det);
    o[4] = __fdiv_rn(a * i - c * g, det);
    o[5] = __fdiv_rn(c * d - a * f, det);
    o[6] = __fdiv_rn(c02, det);
    o[7] = __fdiv_rn(b * g - a * h, det);
    o[8] = __fdiv_rn(a * e - b * d, det);
}

// ---------------------------------------------------------------------------
// Kernel 2: main. One block per (w, b). 256 threads = 8 warps. (R4 skeleton)
//  P1a: logits -> wts[41][32] smem (contiguous float4)
//  P1b: features -> sf[64][36] smem (coalesced global float4)
//  P2 : softmax over d per h (smem partials, proven path)
//  P3 : geometry per (d,h); h-uniformity ballot; normalize+mask wts
//  P4 : warp = (dg, chalf), lane = channel; f regs from sf (LDS.128,
//       conflict-free); wts via broadcast LDS.128; ONE atomic/(d,channel).
// ---------------------------------------------------------------------------
__global__ __launch_bounds__(256) void lss_main(
    const float* __restrict__ intrins,
    const float* __restrict__ rots,
    const float* __restrict__ trans,
    float* __restrict__ out)
{
    __shared__ float wts[DD][FH_];      // logits -> exp -> masked weights
    __shared__ float sf[CCH][FPAD];     // [c][h] feature stage
    __shared__ float pmax[8][FH_];
    __shared__ float psum[8][FH_];
    __shared__ float fullmax[FH_];
    __shared__ float fsum[FH_];
    __shared__ int   binsp[DD];
    __shared__ int   flags[DD];         // 0 = no kept, 1 = uniform, 2 = mixed
    __shared__ int   binh[DD][FH_];
    __shared__ float iR[9], iK[9], tv[3];

    const int w    = blockIdx.x;
    const int b    = blockIdx.y;
    const int tid  = threadIdx.x;
    const int lane = tid & 31;
    const int wg   = tid >> 5;                 // 0..7
    const int c    = ((wg & 1) << 5) + lane;   // phase-4 channel
    const int dg   = wg >> 1;                  // phase-4 d-subgroup (0..3)

    const float* xt = g_xT + ((size_t)b * FW_ + w) * COLH;

    // P1a: logits 41x32 (contiguous) -> smem via float4
    {
        const float4* src = (const float4*)xt;
        float4* dst = (float4*)&wts[0][0];
        for (int i = tid; i < (DD * FH_) / 4; i += 256) dst[i] = src[i];
    }
    // P1b: features 64x32 -> sf[c][h]; global side contiguous float4
    {
        const float4* src = (const float4*)(xt + DD * FH_);
        for (int i = tid; i < (CCH * FH_) / 4; i += 256) {
            float4 v = src[i];
            int cc = i >> 3, h4 = (i & 7) << 2;
            float* p = &sf[cc][h4];
            p[0] = v.x; p[1] = v.y; p[2] = v.z; p[3] = v.w;
        }
    }
    if (tid == 0) {
        float mr[9], mk[9];
#pragma unroll
        for (int k = 0; k < 9; k++) { mr[k] = rots[b * 9 + k]; mk[k] = intrins[b * 9 + k]; }
        inv3(mr, iR);
        inv3(mk, iK);
        tv[0] = trans[b * 3 + 0]; tv[1] = trans[b * 3 + 1]; tv[2] = trans[b * 3 + 2];
    }
    __syncthreads();

    // P2: softmax over d per h (8 partial groups, proven in 18us kernel)
    {
        float pm = -3.402823466e38f;
        for (int d = wg; d < DD; d += 8) pm = fmaxf(pm, wts[d][lane]);
        pmax[wg][lane] = pm;
    }
    __syncthreads();
    if (tid < 32) {
        float m = pmax[0][lane];
#pragma unroll
        for (int g = 1; g < 8; g++) m = fmaxf(m, pmax[g][lane]);
        fullmax[lane] = m;
    }
    __syncthreads();
    {
        float m = fullmax[lane];
        float ps = 0.f;
        for (int d = wg; d < DD; d += 8) {
            float e = __expf(wts[d][lane] - m);
            wts[d][lane] = e;
            ps += e;
        }
        psum[wg][lane] = ps;
    }
    __syncthreads();
    if (tid < 32) {
        float s = psum[0][lane];
#pragma unroll
        for (int g = 1; g < 8; g++) s += psum[g][lane];
        fsum[lane] = s;
    }
    __syncthreads();

    // P3: geometry. warp wg handles d = wg, wg+8, ...; lane = h.
    {
        const float xs = (float)w    * (703.0f / 87.0f);
        const float ys = (float)lane * (255.0f / 31.0f);
        const float r00 = iR[0], r01 = iR[1], r02 = iR[2];
        const float r10 = iR[3], r11 = iR[4], r12 = iR[5];
        const float r20 = iR[6], r21 = iR[7], r22 = iR[8];
        const float k00 = iK[0], k01 = iK[1], k02 = iK[2];
        const float k10 = iK[3], k11 = iK[4], k12 = iK[5];
        const float k20 = iK[6], k21 = iK[7], k22 = iK[8];
        const float t0 = tv[0], t1 = tv[1], t2 = tv[2];
        const float p0 = xs - t0, p1 = ys - t1;
        const float rinv = __frcp_rn(fsum[lane]);

        for (int d = wg; d < DD; d += 8) {
            float p2 = (4.0f + (float)d) - t2;
            float q0 = __fmaf_rn(r00, p0, __fmaf_rn(r01, p1, r02 * p2));
            float q1 = __fmaf_rn(r10, p0, __fmaf_rn(r11, p1, r12 * p2));
            float q2 = __fmaf_rn(r20, p0, __fmaf_rn(r21, p1, r22 * p2));
            float s0 = q0 * q2, s1 = q1 * q2, s2 = q2;
            float g0 = __fmaf_rn(k00, s0, __fmaf_rn(k01, s1, k02 * s2));
            float g1 = __fmaf_rn(k10, s0, __fmaf_rn(k11, s1, k12 * s2));
            float g2 = __fmaf_rn(k20, s0, __fmaf_rn(k21, s1, k22 * s2));
            // truncation toward zero matches astype(int32)
            int c0i = (int)((g0 + 50.0f) / 0.5f);
            int c1i = (int)((g1 + 10.0f) / 20.0f);
            int c2i = (int)(g2 / 0.25f);
            bool kept = (c0i >= 0) & (c0i < NX0_) & (c1i >= 0) & (c1i < 1) &
                        (c2i >= 0) & (c2i < NZ_);
            int sp = c2i * NX0_ + c0i;
            binh[d][lane] = sp;
            float wv = kept ? wts[d][lane] * rinv : 0.0f;
            wts[d][lane] = wv;

            unsigned km = __ballot_sync(0xffffffffu, kept);
            int fl = 0;
            if (km) {
                int src = __ffs(km) - 1;
                int lsp = __shfl_sync(0xffffffffu, sp, src);
                bool ok = (!kept) || (sp == lsp);
                fl = __all_sync(0xffffffffu, ok) ? 1 : 2;
                if (lane == 0) binsp[d] = lsp;
            }
            if (lane == 0) flags[d] = fl;
        }
    }
    __syncthreads();

    // P4: matvec + scatter. f regs via conflict-free LDS.128 from sf;
    // wts rows read as broadcast LDS.128 (128B-aligned rows).
    {
        float f[FH_];
        {
            const float4* sfc = (const float4*)&sf[c][0];
#pragma unroll
            for (int k = 0; k < 8; k++) {
                float4 v = sfc[k];
                f[4 * k + 0] = v.x; f[4 * k + 1] = v.y;
                f[4 * k + 2] = v.z; f[4 * k + 3] = v.w;
            }
        }

        float* ob = out + ((size_t)b * CCH + c) * (NZ_ * NX0_);
        for (int d = dg; d < DD; d += 4) {
            int fl = flags[d];
            if (fl == 0) continue;
            if (fl == 1) {
                const float4* wr = (const float4*)&wts[d][0];
                float a0 = 0.f, a1 = 0.f, a2 = 0.f, a3 = 0.f;
#pragma unroll
                for (int k = 0; k < 8; k++) {
                    float4 wv4 = wr[k];              // broadcast LDS.128
                    a0 = __fmaf_rn(wv4.x, f[4 * k + 0], a0);
                    a1 = __fmaf_rn(wv4.y, f[4 * k + 1], a1);
                    a2 = __fmaf_rn(wv4.z, f[4 * k + 2], a2);
                    a3 = __fmaf_rn(wv4.w, f[4 * k + 3], a3);
                }
                atomicAdd(ob + binsp[d], (a0 + a1) + (a2 + a3));
            } else {
                // generic fallback: per-h scatter
#pragma unroll
                for (int h = 0; h < FH_; h++) {
                    float wv = wts[d][h];
                    if (wv != 0.f) atomicAdd(ob + binh[d][h], wv * f[h]);
                }
            }
        }
    }
}

// ---------------------------------------------------------------------------
extern "C" void kernel_launch(void* const* d_in, const int* in_sizes, int n_in,
                              void* d_out, int out_size) {
    const float* x       = (const float*)d_in[0];
    const float* intrins = (const float*)d_in[1];
    const float* rots    = (const float*)d_in[2];
    const float* trans   = (const float*)d_in[3];
    float* out = (float*)d_out;

    // fused zero-fill + transpose
    dim3 pgrid(COLH / 32, (FW_ + 31) / 32, B_);   // (105, 3, 4)
    lss_prep<<<pgrid, 256>>>(x, out);

    dim3 mgrid(FW_, B_);
    lss_main<<<mgrid, 256>>>(intrins, rots, trans, out);
}